// round 17
// baseline (speedup 1.0000x reference)
#include <cuda_runtime.h>
#include <cstdint>

// ============================================================================
// BinaryConv2D: x(64,56,56,128) NHWC conv w(3,3,128,256) HWIO, SAME, stride 1.
// binarize both -> implicit GEMM on mma.sync m16n8k32 S8 IMMA, S32 accumulate
// (exact: products ±1 as s8 0x01/0xFF, sums <= 1152 in s32; cvt->f32 exact).
// == R17: RATE EXPERIMENT — swap e4m3 QMMA (pinned at 63% tensor across 10
// variants, ~24cyc effective interval) for legacy s8 IMMA, which on several
// architectures runs the 8-bit path at 2x the fp8-f16acc rate. ==
// CTA: 64 px (8h x 8w, zero waste 56=7x8) x 128 outch. 256 thr, 8 warps
// (2M x 4N), warp tile 32px x 32oc: s32 acc = 32 regs (iron register law:
// acc<=32, total<=85, occ 3). Grid 6272; B L2 traffic identical to R15.
//   A: SMEM halo 10x10 px (14.4KB), padded-linear 144B rows, loaded once,
//      kh x3 rolled / kw,kk unrolled, NO mainloop barriers.
//   B: no smem; fragment-ordered, uint4 = 2 k-steps x 1 n-group, __ldg just
//      in time (R9: batching => spills). Per kk: 4 LDSM + 4 LDG + 16 MMA.
// (tcgen05/TMEM unavailable: harness ptxas targets base sm_103 — proven R1.)
// ============================================================================

constexpr int X_ELEMS = 64 * 56 * 56 * 128;   // 25,690,112
constexpr int WF_U4   = 9 * 32 * 2 * 32;      // 18,432 uint4 = 294,912 B
constexpr int X_BLOCKS = X_ELEMS / 8 / 256;   // 12,544

__device__ uint8_t g_xq[X_ELEMS];             // binarized x, NHWC s8 (+1/-1)
__device__ uint4   g_wf[WF_U4];               // weights, fragment-ordered s8

// ---------------------------------------------------------------------------
// merged preprocessing: s8 +1 = 0x01, -1 = 0xFF
// ---------------------------------------------------------------------------
__global__ void prep_kernel(const float* __restrict__ x,
                            const float* __restrict__ w) {
    if (blockIdx.x < X_BLOCKS) {
        int t = blockIdx.x * 256 + threadIdx.x;
        int base = t * 8;
        const float4* p = reinterpret_cast<const float4*>(x + base);
        float4 v0 = p[0], v1 = p[1];
        uint32_t lo = (v0.x >= 0.0f ? 0x01u : 0xFFu)        |
                      ((v0.y >= 0.0f ? 0x01u : 0xFFu) << 8)  |
                      ((v0.z >= 0.0f ? 0x01u : 0xFFu) << 16) |
                      ((v0.w >= 0.0f ? 0x01u : 0xFFu) << 24);
        uint32_t hi = (v1.x >= 0.0f ? 0x01u : 0xFFu)        |
                      ((v1.y >= 0.0f ? 0x01u : 0xFFu) << 8)  |
                      ((v1.z >= 0.0f ? 0x01u : 0xFFu) << 16) |
                      ((v1.w >= 0.0f ? 0x01u : 0xFFu) << 24);
        *reinterpret_cast<uint2*>(g_xq + base) = make_uint2(lo, hi);
    } else {
        // fragment order: u4 = ((tap*32 + g)*2 + kk)*32 + lane
        //   outch o = g*8 + (lane>>2),  g = 0..31 covers all 256 outch
        //   {x,y} = B-frag regs for k=2kk, {z,w} for k=2kk+1 (m16n8k32 colB)
        //   b0 bytes b2: ch = k*32 + (lane&3)*4 + b2 ; b1: +16
        int u = (blockIdx.x - X_BLOCKS) * 256 + threadIdx.x;
        if (u >= WF_U4) return;
        int lane = u & 31;
        int kk   = (u >> 5) & 1;
        int g    = (u >> 6) & 31;
        int tap  = u >> 11;
        int o = g * 8 + (lane >> 2);
        uint32_t r[4];
        #pragma unroll
        for (int kp = 0; kp < 2; ++kp) {
            int cb = (2 * kk + kp) * 32 + (lane & 3) * 4;
            uint32_t r0 = 0, r1 = 0;
            #pragma unroll
            for (int b2 = 0; b2 < 4; ++b2) {
                float v0 = w[(tap * 128 + cb + b2) * 256 + o];       // HWIO
                float v1 = w[(tap * 128 + cb + 16 + b2) * 256 + o];
                r0 |= (v0 >= 0.0f ? 0x01u : 0xFFu) << (8 * b2);
                r1 |= (v1 >= 0.0f ? 0x01u : 0xFFu) << (8 * b2);
            }
            r[2 * kp] = r0; r[2 * kp + 1] = r1;
        }
        g_wf[u] = make_uint4(r[0], r[1], r[2], r[3]);
    }
}

// ---------------------------------------------------------------------------
// PTX helpers
// ---------------------------------------------------------------------------
static __device__ __forceinline__ void ldmatrix_x4(uint32_t& r0, uint32_t& r1,
                                                   uint32_t& r2, uint32_t& r3,
                                                   uint32_t addr) {
    asm volatile("ldmatrix.sync.aligned.m8n8.x4.shared.b16 {%0,%1,%2,%3}, [%4];"
                 : "=r"(r0), "=r"(r1), "=r"(r2), "=r"(r3) : "r"(addr));
}

// s8 IMMA with s32 accumulators (4 regs; exact integer accumulation)
static __device__ __forceinline__ void mma_s8(int32_t* c, const uint32_t* a,
                                              uint32_t b0, uint32_t b1) {
    asm volatile(
        "mma.sync.aligned.m16n8k32.row.col.s32.s8.s8.s32 "
        "{%0,%1,%2,%3}, {%4,%5,%6,%7}, {%8,%9}, {%0,%1,%2,%3};"
        : "+r"(c[0]), "+r"(c[1]), "+r"(c[2]), "+r"(c[3])
        : "r"(a[0]), "r"(a[1]), "r"(a[2]), "r"(a[3]), "r"(b0), "r"(b1));
}

static __device__ __forceinline__ void cp16(uint32_t dst, const void* src, int srcsize) {
    asm volatile("cp.async.cg.shared.global [%0], [%1], 16, %2;"
                 :: "r"(dst), "l"(src), "r"(srcsize) : "memory");
}

// ---------------------------------------------------------------------------
// main kernel: 256 threads, 8 warps (2M x 4N), warp tile 32px x 32oc
// SMEM: A halo only, 100 rows x 144B stride = 14,400 B
// ---------------------------------------------------------------------------
constexpr int ROWB = 144;
constexpr int SMEM_TOTAL = 100 * ROWB;        // 14,400

__global__ void __launch_bounds__(256, 3)
conv_s8_kernel(float* __restrict__ out) {
    extern __shared__ char smem[];
    uint32_t sbase = (uint32_t)__cvta_generic_to_shared(smem);

    int tid  = threadIdx.x;
    int lane = tid & 31;
    int wid  = tid >> 5;
    int warp_m = wid & 1;        // 0..1 -> 32 pixels each
    int warp_n = wid >> 1;       // 0..3 -> 32 outch each

    // tile decode: blockIdx = ((img*49 + ht*7 + wt) << 1) | ntile
    int b = blockIdx.x;
    int ntile = b & 1;
    int mt = b >> 1;
    int img = mt / 49;
    int rr  = mt - img * 49;
    int ht  = rr / 7;
    int wt  = rr - ht * 7;
    int h0 = ht * 8;
    int w0 = wt * 8;
    int n0 = ntile * 128;

    // ---- stage A halo (10h x 10w pixels, zero-filled outside image) ----
    for (int idx = tid; idx < 800; idx += 256) {         // 100 rows x 8 chunks
        int row = idx >> 3, ch = idx & 7;
        int hr = row / 10;
        int wc = row - hr * 10;
        int hh = h0 + hr - 1;
        int ww = w0 + wc - 1;
        bool v = ((unsigned)hh < 56u) && ((unsigned)ww < 56u);
        const char* src = v ? (const char*)(g_xq + (((img * 56 + hh) * 56 + ww) << 7))
                            : (const char*)g_xq;
        cp16(sbase + row * ROWB + ch * 16, src + ch * 16, v ? 16 : 0);
    }
    asm volatile("cp.async.commit_group;" ::: "memory");
    asm volatile("cp.async.wait_group 0;" ::: "memory");
    __syncthreads();

    // ---- per-lane ldmatrix base addresses (linear, conflict-free) ----
    int lane15 = lane & 15;
    int lanehi = lane >> 4;
    uint32_t abase[2];
    #pragma unroll
    for (int mi = 0; mi < 2; ++mi) {
        int p = warp_m * 32 + mi * 16 + lane15;          // pixel index 0..63
        int hrow = (p >> 3) * 10 + (p & 7);              // halo row at tap (0,0)
        abase[mi] = sbase + hrow * ROWB + lanehi * 16;
    }
    // B fragment base for this thread: g = ntile*16 + warp_n*4 + ni
    const uint4* wf0 = g_wf + (uint32_t)(((ntile * 16 + warp_n * 4) * 2) * 32 + lane);

    int32_t acc[2][4][4];                                // s32 accumulators
    #pragma unroll
    for (int mi = 0; mi < 2; ++mi)
        #pragma unroll
        for (int ni = 0; ni < 4; ++ni)
            #pragma unroll
            for (int q = 0; q < 4; ++q) acc[mi][ni][q] = 0;

    // ---- mainloop: kh x3 (rolled), kw x3 + kk x2 fully unrolled ----
    // per kk: 4 LDSM + 4 LDG.128 + 16 MMA (67% MMA issue mix)
    for (int kh = 0; kh < 3; ++kh) {
        uint32_t akh0 = abase[0] + (uint32_t)(kh * 10 * ROWB);
        uint32_t akh1 = abase[1] + (uint32_t)(kh * 10 * ROWB);
        const uint4* wkh = wf0 + (uint32_t)(kh * 3 * 2048);  // 3 taps * 64*32
        #pragma unroll
        for (int kw = 0; kw < 3; ++kw) {
            const uint4* wft = wkh + (uint32_t)(kw * 2048);
            #pragma unroll
            for (int kk = 0; kk < 2; ++kk) {
                uint32_t a[2][2][4];                      // [kpar][mi][4]
                #pragma unroll
                for (int kp = 0; kp < 2; ++kp) {
                    uint32_t koff = (uint32_t)(kw * ROWB + (2 * kk + kp) * 32);
                    ldmatrix_x4(a[kp][0][0], a[kp][0][1], a[kp][0][2], a[kp][0][3],
                                akh0 + koff);
                    ldmatrix_x4(a[kp][1][0], a[kp][1][1], a[kp][1][2], a[kp][1][3],
                                akh1 + koff);
                }
                const uint4* wfk = wft + (uint32_t)(kk * 32);
                #pragma unroll
                for (int ni = 0; ni < 4; ++ni) {
                    uint4 bv = __ldg(wfk + ni * 64);      // g stride = 2*32 u4
                    mma_s8(acc[0][ni], a[0][0], bv.x, bv.y);
                    mma_s8(acc[1][ni], a[0][1], bv.x, bv.y);
                    mma_s8(acc[0][ni], a[1][0], bv.z, bv.w);
                    mma_s8(acc[1][ni], a[1][1], bv.z, bv.w);
                }
            }
        }
    }

    // ---- epilogue: s32 -> f32 stores (exact; all 64 px in-image) ----
    int colbase = n0 + warp_n * 32 + (lane & 3) * 2;
    #pragma unroll
    for (int mi = 0; mi < 2; ++mi) {
        #pragma unroll
        for (int half = 0; half < 2; ++half) {
            int p = warp_m * 32 + mi * 16 + half * 8 + (lane >> 2);
            int hh = h0 + (p >> 3);
            int ww = w0 + (p & 7);
            float* op = out + (((img * 56 + hh) * 56 + ww) << 8);
            #pragma unroll
            for (int ni = 0; ni < 4; ++ni) {
                float2 v;
                v.x = (float)acc[mi][ni][half * 2 + 0];
                v.y = (float)acc[mi][ni][half * 2 + 1];
                *reinterpret_cast<float2*>(op + colbase + ni * 8) = v;
            }
        }
    }
}

// ---------------------------------------------------------------------------
// launch
// ---------------------------------------------------------------------------
extern "C" void kernel_launch(void* const* d_in, const int* in_sizes, int n_in,
                              void* d_out, int out_size) {
    const float* x = (const float*)d_in[0];
    const float* w = (const float*)d_in[1];
    float* out = (float*)d_out;

    prep_kernel<<<X_BLOCKS + (WF_U4 + 255) / 256, 256>>>(x, w);

    cudaFuncSetAttribute(conv_s8_kernel,
                         cudaFuncAttributeMaxDynamicSharedMemorySize, SMEM_TOTAL);
    // 64 images * 7h * 7w * 2 ntiles = 6272 CTAs (zero wasted MMAs)
    conv_s8_kernel<<<6272, 256, SMEM_TOTAL>>>(out);
}